// round 1
// baseline (speedup 1.0000x reference)
#include <cuda_runtime.h>

#define N_NODES 50000
#define N_EDGES 800000
#define E_TOT   (N_EDGES + N_NODES)
#define D 128
#define H 4

// ---------------- scratch (static device globals; no allocs) ----------------
__device__ __align__(16) float g_h  [N_NODES * D];
__device__ __align__(16) float g_h2 [N_NODES * D];
__device__ __align__(16) float g_xp [N_NODES * D];
__device__ __align__(16) float g_als[N_NODES * H];
__device__ __align__(16) float g_ald[N_NODES * H];
__device__ int g_deg[N_NODES];
__device__ int g_rowptr[N_NODES + 1];
__device__ int g_wp[N_NODES];
__device__ int g_col[E_TOT];
__device__ int g_bsum[64];

// ---------------- CSR build ----------------
__global__ void k_init() {
    int i = blockIdx.x * blockDim.x + threadIdx.x;
    if (i < N_NODES) g_deg[i] = 1;            // self loop pre-counted
}

__global__ void k_count(const int* __restrict__ ei) {
    int i = blockIdx.x * blockDim.x + threadIdx.x;
    if (i < N_EDGES) atomicAdd(&g_deg[ei[N_EDGES + i]], 1);
}

__global__ void k_scan1() {
    __shared__ int sm[1024];
    int i = blockIdx.x * 1024 + threadIdx.x;
    int v = (i < N_NODES) ? g_deg[i] : 0;
    sm[threadIdx.x] = v;
    __syncthreads();
    for (int off = 1; off < 1024; off <<= 1) {
        int t = (threadIdx.x >= off) ? sm[threadIdx.x - off] : 0;
        __syncthreads();
        sm[threadIdx.x] += t;
        __syncthreads();
    }
    if (i < N_NODES) g_rowptr[i] = sm[threadIdx.x] - v;   // exclusive
    if (threadIdx.x == 1023) g_bsum[blockIdx.x] = sm[1023];
}

__global__ void k_scan2(int nb) {
    if (threadIdx.x == 0) {
        int run = 0;
        for (int b = 0; b < nb; b++) { int t = g_bsum[b]; g_bsum[b] = run; run += t; }
    }
}

__global__ void k_scan3() {
    int i = blockIdx.x * blockDim.x + threadIdx.x;
    if (i < N_NODES) {
        int r = g_rowptr[i] + g_bsum[i >> 10];
        g_rowptr[i] = r;
        g_wp[i] = r;
    }
    if (i == 0) g_rowptr[N_NODES] = E_TOT;
}

__global__ void k_scatter(const int* __restrict__ ei) {
    int i = blockIdx.x * blockDim.x + threadIdx.x;
    if (i < N_NODES) {
        int p = atomicAdd(&g_wp[i], 1);
        g_col[p] = i;                          // self loop
    } else if (i < N_NODES + N_EDGES) {
        int j = i - N_NODES;
        int s = ei[j], d = ei[N_EDGES + j];
        int p = atomicAdd(&g_wp[d], 1);
        g_col[p] = s;
    }
}

// ---------------- SGEMM: C[N,128] = A[N,128] @ W[128,128] (+bias) ----------------
// BM=64, BN=64, BK=16, 256 threads, 4x4 register tile per thread.
__global__ void k_gemm(const float* Aext, int asel,
                       const float* __restrict__ W,
                       const float* __restrict__ bias,
                       int csel) {
    __shared__ float As[16][68];   // As[k][m]  (stride 68 -> 16B aligned rows)
    __shared__ float Bs[16][68];   // Bs[k][n]
    const float* A = Aext ? Aext : (asel == 0 ? g_h : g_h2);
    float* Cp = (csel == 0 ? g_h : (csel == 1 ? g_h2 : g_xp));
    int bm = blockIdx.x * 64, bn = blockIdx.y * 64;
    int tid = threadIdx.x;
    int tx = tid & 15, ty = tid >> 4;
    float acc[4][4] = {};
    int arow = tid >> 2, ak = (tid & 3) << 2;
    int brow = tid >> 4, bc = (tid & 15) << 2;
    for (int k0 = 0; k0 < 128; k0 += 16) {
        float4 av = make_float4(0.f, 0.f, 0.f, 0.f);
        if (bm + arow < N_NODES)
            av = *(const float4*)(A + (size_t)(bm + arow) * D + k0 + ak);
        As[ak + 0][arow] = av.x; As[ak + 1][arow] = av.y;
        As[ak + 2][arow] = av.z; As[ak + 3][arow] = av.w;
        *(float4*)&Bs[brow][bc] =
            *(const float4*)(W + (size_t)(k0 + brow) * D + bn + bc);
        __syncthreads();
#pragma unroll
        for (int k = 0; k < 16; k++) {
            float4 a = *(const float4*)&As[k][ty * 4];
            float4 b = *(const float4*)&Bs[k][tx * 4];
            float ar[4] = {a.x, a.y, a.z, a.w};
            float br[4] = {b.x, b.y, b.z, b.w};
#pragma unroll
            for (int i = 0; i < 4; i++)
#pragma unroll
                for (int j = 0; j < 4; j++)
                    acc[i][j] += ar[i] * br[j];
        }
        __syncthreads();
    }
#pragma unroll
    for (int i = 0; i < 4; i++) {
        int row = bm + ty * 4 + i;
        if (row < N_NODES) {
#pragma unroll
            for (int j = 0; j < 4; j++) {
                float v = acc[i][j];
                if (bias) v += bias[bn + tx * 4 + j];
                Cp[(size_t)row * D + bn + tx * 4 + j] = v;
            }
        }
    }
}

// ---------------- per-node attention logits: al = <xp[n,h,:], a[h,:]> ----------------
__global__ void k_al(const float* __restrict__ a_src, const float* __restrict__ a_dst) {
    int warp = (blockIdx.x * blockDim.x + threadIdx.x) >> 5;
    if (warp >= N_NODES) return;
    int lane = threadIdx.x & 31;
    int hh = lane >> 3;
    int co = (lane & 7) << 2;   // channel offset within head
    float4 xv = *(const float4*)(g_xp + (size_t)warp * D + lane * 4);
    float4 sv = *(const float4*)(a_src + hh * 32 + co);
    float4 dv = *(const float4*)(a_dst + hh * 32 + co);
    float ps = xv.x * sv.x + xv.y * sv.y + xv.z * sv.z + xv.w * sv.w;
    float pd = xv.x * dv.x + xv.y * dv.y + xv.z * dv.z + xv.w * dv.w;
#pragma unroll
    for (int off = 4; off >= 1; off >>= 1) {
        ps += __shfl_xor_sync(0xffffffffu, ps, off);
        pd += __shfl_xor_sync(0xffffffffu, pd, off);
    }
    if ((lane & 7) == 0) {
        g_als[warp * H + hh] = ps;
        g_ald[warp * H + hh] = pd;
    }
}

// ---------------- softmax-aggregate: one warp per destination node ----------------
__global__ void k_agg(int in_sel, float* out_ext, int out_sel,
                      const float* __restrict__ bias, int relu_res) {
    int n = (blockIdx.x * blockDim.x + threadIdx.x) >> 5;
    if (n >= N_NODES) return;
    int lane = threadIdx.x & 31;
    const float* xin = (in_sel == 0) ? g_h : g_h2;
    float* outp = out_ext ? out_ext : (out_sel == 0 ? g_h : g_h2);
    int beg = g_rowptr[n], end = g_rowptr[n + 1];
    float ald0 = g_ald[n * 4 + 0], ald1 = g_ald[n * 4 + 1];
    float ald2 = g_ald[n * 4 + 2], ald3 = g_ald[n * 4 + 3];

    // pass 1: per-head max (edges split across lanes, then warp-reduce)
    float mx0 = -1e30f, mx1 = -1e30f, mx2 = -1e30f, mx3 = -1e30f;
    for (int j = beg + lane; j < end; j += 32) {
        int s = g_col[j];
        const float* as = g_als + (size_t)s * 4;
        float e0 = as[0] + ald0; e0 = e0 > 0.f ? e0 : 0.2f * e0; mx0 = fmaxf(mx0, e0);
        float e1 = as[1] + ald1; e1 = e1 > 0.f ? e1 : 0.2f * e1; mx1 = fmaxf(mx1, e1);
        float e2 = as[2] + ald2; e2 = e2 > 0.f ? e2 : 0.2f * e2; mx2 = fmaxf(mx2, e2);
        float e3 = as[3] + ald3; e3 = e3 > 0.f ? e3 : 0.2f * e3; mx3 = fmaxf(mx3, e3);
    }
#pragma unroll
    for (int off = 16; off >= 1; off >>= 1) {
        mx0 = fmaxf(mx0, __shfl_xor_sync(0xffffffffu, mx0, off));
        mx1 = fmaxf(mx1, __shfl_xor_sync(0xffffffffu, mx1, off));
        mx2 = fmaxf(mx2, __shfl_xor_sync(0xffffffffu, mx2, off));
        mx3 = fmaxf(mx3, __shfl_xor_sync(0xffffffffu, mx3, off));
    }
    int hh = lane >> 3;
    float m  = (hh == 0) ? mx0 : (hh == 1) ? mx1 : (hh == 2) ? mx2 : mx3;
    float ad = (hh == 0) ? ald0 : (hh == 1) ? ald1 : (hh == 2) ? ald2 : ald3;

    // pass 2: every lane walks all edges; lane owns channels [4*lane, 4*lane+4)
    float4 acc = make_float4(0.f, 0.f, 0.f, 0.f);
    float ssum = 0.f;
    int s_next = (beg < end) ? g_col[beg] : 0;
    for (int j = beg; j < end; j++) {
        int s = s_next;
        if (j + 1 < end) s_next = g_col[j + 1];       // prefetch next index
        float e = g_als[(size_t)s * 4 + hh] + ad;
        e = e > 0.f ? e : 0.2f * e;
        float p = __expf(e - m);
        ssum += p;
        float4 xv = *(const float4*)(g_xp + (size_t)s * D + lane * 4);
        acc.x += p * xv.x; acc.y += p * xv.y;
        acc.z += p * xv.z; acc.w += p * xv.w;
    }
    float inv = 1.f / ssum;
    float4 bv = *(const float4*)(bias + lane * 4);
    float4 o;
    o.x = acc.x * inv + bv.x;
    o.y = acc.y * inv + bv.y;
    o.z = acc.z * inv + bv.z;
    o.w = acc.w * inv + bv.w;
    if (relu_res) {
        float4 r = *(const float4*)(xin + (size_t)n * D + lane * 4);
        o.x = fmaxf(o.x + r.x, 0.f);
        o.y = fmaxf(o.y + r.y, 0.f);
        o.z = fmaxf(o.z + r.z, 0.f);
        o.w = fmaxf(o.w + r.w, 0.f);
    }
    *(float4*)(outp + (size_t)n * D + lane * 4) = o;
}

// ---------------- launch ----------------
extern "C" void kernel_launch(void* const* d_in, const int* in_sizes, int n_in,
                              void* d_out, int out_size) {
    const float* x   = (const float*)d_in[0];
    const int*   ei  = (const int*)  d_in[1];
    const float* w0  = (const float*)d_in[2];
    const float* b0  = (const float*)d_in[3];
    const float* w1  = (const float*)d_in[4];
    const float* as1 = (const float*)d_in[5];
    const float* ad1 = (const float*)d_in[6];
    const float* b1  = (const float*)d_in[7];
    const float* w2  = (const float*)d_in[8];
    const float* as2 = (const float*)d_in[9];
    const float* ad2 = (const float*)d_in[10];
    const float* b2  = (const float*)d_in[11];
    const float* w3  = (const float*)d_in[12];
    const float* as3 = (const float*)d_in[13];
    const float* ad3 = (const float*)d_in[14];
    const float* b3  = (const float*)d_in[15];
    float* out = (float*)d_out;

    // CSR by destination (rebuilt every replay; deterministic counts)
    k_init<<<(N_NODES + 255) / 256, 256>>>();
    k_count<<<(N_EDGES + 255) / 256, 256>>>(ei);
    int nb = (N_NODES + 1023) / 1024;
    k_scan1<<<nb, 1024>>>();
    k_scan2<<<1, 32>>>(nb);
    k_scan3<<<(N_NODES + 255) / 256, 256>>>();
    k_scatter<<<(N_NODES + N_EDGES + 255) / 256, 256>>>(ei);

    dim3 ggrid((N_NODES + 63) / 64, 2);
    int wgrid = (N_NODES * 32) / 256;   // 6250 blocks, 1 warp per node

    // h0 = x @ w0 + b0  -> g_h
    k_gemm<<<ggrid, 256>>>(x, 0, w0, b0, 0);

    // layer 1: in g_h -> out g_h2 (relu + residual)
    k_gemm<<<ggrid, 256>>>(nullptr, 0, w1, nullptr, 2);
    k_al<<<wgrid, 256>>>(as1, ad1);
    k_agg<<<wgrid, 256>>>(0, nullptr, 1, b1, 1);

    // layer 2: in g_h2 -> out g_h (relu + residual)
    k_gemm<<<ggrid, 256>>>(nullptr, 1, w2, nullptr, 2);
    k_al<<<wgrid, 256>>>(as2, ad2);
    k_agg<<<wgrid, 256>>>(1, nullptr, 0, b2, 1);

    // layer 3: in g_h -> d_out (plain)
    k_gemm<<<ggrid, 256>>>(nullptr, 0, w3, nullptr, 2);
    k_al<<<wgrid, 256>>>(as3, ad3);
    k_agg<<<wgrid, 256>>>(0, out, 0, b3, 0);
}

// round 2
// speedup vs baseline: 1.5705x; 1.5705x over previous
#include <cuda_runtime.h>
#include <cstdint>

#define N_NODES 50000
#define N_EDGES 800000
#define E_TOT   (N_EDGES + N_NODES)
#define D 128
#define H 4

// ---------------- scratch (static device globals; no allocs) ----------------
__device__ __align__(16) float g_h  [N_NODES * D];
__device__ __align__(16) float g_h2 [N_NODES * D];
__device__ __align__(16) float g_xp [N_NODES * D];
__device__ __align__(16) float g_als[N_NODES * H];
__device__ __align__(16) float g_ald[N_NODES * H];
__device__ int g_deg[N_NODES];
__device__ int g_rowptr[N_NODES + 1];
__device__ int g_wp[N_NODES];
__device__ int g_col[E_TOT];
__device__ int g_bsum[64];

// ---------------- CSR build ----------------
__global__ void k_init() {
    int i = blockIdx.x * blockDim.x + threadIdx.x;
    if (i < N_NODES) g_deg[i] = 1;            // self loop pre-counted
}

__global__ void k_count(const int* __restrict__ ei) {
    int i = blockIdx.x * blockDim.x + threadIdx.x;
    if (i < N_EDGES) atomicAdd(&g_deg[ei[N_EDGES + i]], 1);
}

__global__ void k_scan1() {
    __shared__ int sm[1024];
    int i = blockIdx.x * 1024 + threadIdx.x;
    int v = (i < N_NODES) ? g_deg[i] : 0;
    sm[threadIdx.x] = v;
    __syncthreads();
    for (int off = 1; off < 1024; off <<= 1) {
        int t = (threadIdx.x >= off) ? sm[threadIdx.x - off] : 0;
        __syncthreads();
        sm[threadIdx.x] += t;
        __syncthreads();
    }
    if (i < N_NODES) g_rowptr[i] = sm[threadIdx.x] - v;   // exclusive
    if (threadIdx.x == 1023) g_bsum[blockIdx.x] = sm[1023];
}

__global__ void k_scan2(int nb) {          // parallel 64-wide Hillis-Steele
    __shared__ int sm[64];
    int t = threadIdx.x;
    int v = (t < nb) ? g_bsum[t] : 0;
    sm[t] = v;
    __syncthreads();
#pragma unroll
    for (int off = 1; off < 64; off <<= 1) {
        int x = (t >= off) ? sm[t - off] : 0;
        __syncthreads();
        sm[t] += x;
        __syncthreads();
    }
    if (t < nb) g_bsum[t] = sm[t] - v;     // exclusive block offsets
}

__global__ void k_scan3() {
    int i = blockIdx.x * blockDim.x + threadIdx.x;
    if (i < N_NODES) {
        int r = g_rowptr[i] + g_bsum[i >> 10];
        g_rowptr[i] = r;
        g_wp[i] = r;
    }
    if (i == 0) g_rowptr[N_NODES] = E_TOT;
}

__global__ void k_scatter(const int* __restrict__ ei) {
    int i = blockIdx.x * blockDim.x + threadIdx.x;
    if (i < N_NODES) {
        int p = atomicAdd(&g_wp[i], 1);
        g_col[p] = i;                          // self loop
    } else if (i < N_NODES + N_EDGES) {
        int j = i - N_NODES;
        int s = ei[j], d = ei[N_EDGES + j];
        int p = atomicAdd(&g_wp[d], 1);
        g_col[p] = s;
    }
}

// ---------------- tf32 tensor-core GEMM ----------------
// C[N,128] = A[N,128] @ W[128,128] (+bias), BM=128 BN=128 BK=32, 256 thr.
// 8 warps: warp_m = wid&3 (32 rows), warp_n = wid>>2 (64 cols).
// mma.sync.aligned.m16n8k8 tf32 (fallback HMMA on sm_103a).

__device__ __forceinline__ uint32_t f2tf32(float f) {
    uint32_t r;
    asm("cvt.rna.tf32.f32 %0, %1;" : "=r"(r) : "f"(f));
    return r;
}

__global__ void __launch_bounds__(256) k_gemm_tc(
        const float* Aext, int asel,
        const float* __restrict__ W,
        const float* __restrict__ bias,
        int csel) {
    __shared__ uint32_t As[128 * 36];   // [m][k], stride 36 (bank-clean frags)
    __shared__ uint32_t Bs[32 * 136];   // [k][n], stride 136

    const float* A = Aext ? Aext : (asel == 0 ? g_h : g_h2);
    float* Cp = (csel == 0 ? g_h : (csel == 1 ? g_h2 : g_xp));

    const int bm = blockIdx.x * 128;
    const int tid = threadIdx.x;
    const int wid = tid >> 5, lane = tid & 31;
    const int g = lane >> 2, tig = lane & 3;
    const int wm = (wid & 3) * 32;       // warp row base within tile
    const int wn = (wid >> 2) * 64;      // warp col base within tile

    float acc[2][8][4];
#pragma unroll
    for (int mt = 0; mt < 2; mt++)
#pragma unroll
        for (int nt = 0; nt < 8; nt++)
#pragma unroll
            for (int q = 0; q < 4; q++) acc[mt][nt][q] = 0.f;

    for (int k0 = 0; k0 < 128; k0 += 32) {
        // stage A tile: 128x32 floats, 4 float4 per thread
#pragma unroll
        for (int it = 0; it < 4; it++) {
            int idx = tid + 256 * it;
            int row = idx >> 3, c4 = (idx & 7) << 2;
            float4 v = make_float4(0.f, 0.f, 0.f, 0.f);
            if (bm + row < N_NODES)
                v = *(const float4*)(A + (size_t)(bm + row) * D + k0 + c4);
            uint32_t* p = &As[row * 36 + c4];
            p[0] = f2tf32(v.x); p[1] = f2tf32(v.y);
            p[2] = f2tf32(v.z); p[3] = f2tf32(v.w);
        }
        // stage B tile: 32x128 floats
#pragma unroll
        for (int it = 0; it < 4; it++) {
            int idx = tid + 256 * it;
            int row = idx >> 5, c4 = (idx & 31) << 2;
            float4 v = *(const float4*)(W + (size_t)(k0 + row) * D + c4);
            uint32_t* p = &Bs[row * 136 + c4];
            p[0] = f2tf32(v.x); p[1] = f2tf32(v.y);
            p[2] = f2tf32(v.z); p[3] = f2tf32(v.w);
        }
        __syncthreads();

#pragma unroll
        for (int kk = 0; kk < 32; kk += 8) {
            uint32_t a[2][4], b[8][2];
#pragma unroll
            for (int mt = 0; mt < 2; mt++) {
                int r0 = wm + mt * 16 + g;
                a[mt][0] = As[r0 * 36 + kk + tig];
                a[mt][1] = As[(r0 + 8) * 36 + kk + tig];
                a[mt][2] = As[r0 * 36 + kk + tig + 4];
                a[mt][3] = As[(r0 + 8) * 36 + kk + tig + 4];
            }
#pragma unroll
            for (int nt = 0; nt < 8; nt++) {
                int c0 = wn + nt * 8 + g;
                b[nt][0] = Bs[(kk + tig) * 136 + c0];
                b[nt][1] = Bs[(kk + tig + 4) * 136 + c0];
            }
#pragma unroll
            for (int mt = 0; mt < 2; mt++)
#pragma unroll
                for (int nt = 0; nt < 8; nt++) {
                    asm volatile(
                        "mma.sync.aligned.m16n8k8.row.col.f32.tf32.tf32.f32 "
                        "{%0,%1,%2,%3}, {%4,%5,%6,%7}, {%8,%9}, {%0,%1,%2,%3};"
                        : "+f"(acc[mt][nt][0]), "+f"(acc[mt][nt][1]),
                          "+f"(acc[mt][nt][2]), "+f"(acc[mt][nt][3])
                        : "r"(a[mt][0]), "r"(a[mt][1]),
                          "r"(a[mt][2]), "r"(a[mt][3]),
                          "r"(b[nt][0]), "r"(b[nt][1]));
                }
        }
        __syncthreads();
    }

    // epilogue: c0,c1 -> (row, col..col+1); c2,c3 -> (row+8, ...)
#pragma unroll
    for (int mt = 0; mt < 2; mt++) {
        int row = bm + wm + mt * 16 + g;
#pragma unroll
        for (int nt = 0; nt < 8; nt++) {
            int col = wn + nt * 8 + 2 * tig;
            float bx = bias ? bias[col] : 0.f;
            float by = bias ? bias[col + 1] : 0.f;
            if (row < N_NODES) {
                float2* p = (float2*)(Cp + (size_t)row * D + col);
                *p = make_float2(acc[mt][nt][0] + bx, acc[mt][nt][1] + by);
            }
            if (row + 8 < N_NODES) {
                float2* p = (float2*)(Cp + (size_t)(row + 8) * D + col);
                *p = make_float2(acc[mt][nt][2] + bx, acc[mt][nt][3] + by);
            }
        }
    }
}

// ---------------- per-node attention logits: al = <xp[n,h,:], a[h,:]> ----------------
__global__ void k_al(const float* __restrict__ a_src, const float* __restrict__ a_dst) {
    int warp = (blockIdx.x * blockDim.x + threadIdx.x) >> 5;
    if (warp >= N_NODES) return;
    int lane = threadIdx.x & 31;
    int hh = lane >> 3;
    int co = (lane & 7) << 2;   // channel offset within head
    float4 xv = *(const float4*)(g_xp + (size_t)warp * D + lane * 4);
    float4 sv = *(const float4*)(a_src + hh * 32 + co);
    float4 dv = *(const float4*)(a_dst + hh * 32 + co);
    float ps = xv.x * sv.x + xv.y * sv.y + xv.z * sv.z + xv.w * sv.w;
    float pd = xv.x * dv.x + xv.y * dv.y + xv.z * dv.z + xv.w * dv.w;
#pragma unroll
    for (int off = 4; off >= 1; off >>= 1) {
        ps += __shfl_xor_sync(0xffffffffu, ps, off);
        pd += __shfl_xor_sync(0xffffffffu, pd, off);
    }
    if ((lane & 7) == 0) {
        g_als[warp * H + hh] = ps;
        g_ald[warp * H + hh] = pd;
    }
}

// ---------------- softmax-aggregate: one warp per destination node ----------------
// Single pass, no max subtraction (logits bounded; exp() cannot overflow; the
// max-shift is a mathematical identity for softmax).
__global__ void k_agg(int in_sel, float* out_ext, int out_sel,
                      const float* __restrict__ bias, int relu_res) {
    int n = (blockIdx.x * blockDim.x + threadIdx.x) >> 5;
    if (n >= N_NODES) return;
    int lane = threadIdx.x & 31;
    const float* xin = (in_sel == 0) ? g_h : g_h2;
    float* outp = out_ext ? out_ext : (out_sel == 0 ? g_h : g_h2);
    int beg = g_rowptr[n], end = g_rowptr[n + 1];
    int hh = lane >> 3;
    float ad = g_ald[n * 4 + hh];

    float4 acc = make_float4(0.f, 0.f, 0.f, 0.f);
    float ssum = 0.f;
    int s_next = (beg < end) ? g_col[beg] : 0;
    for (int j = beg; j < end; j++) {
        int s = s_next;
        if (j + 1 < end) s_next = g_col[j + 1];       // prefetch next index
        float e = g_als[(size_t)s * 4 + hh] + ad;
        e = e > 0.f ? e : 0.2f * e;
        float p = __expf(e);
        ssum += p;
        float4 xv = *(const float4*)(g_xp + (size_t)s * D + lane * 4);
        acc.x += p * xv.x; acc.y += p * xv.y;
        acc.z += p * xv.z; acc.w += p * xv.w;
    }
    float inv = 1.f / ssum;
    float4 bv = *(const float4*)(bias + lane * 4);
    float4 o;
    o.x = acc.x * inv + bv.x;
    o.y = acc.y * inv + bv.y;
    o.z = acc.z * inv + bv.z;
    o.w = acc.w * inv + bv.w;
    if (relu_res) {
        float4 r = *(const float4*)(xin + (size_t)n * D + lane * 4);
        o.x = fmaxf(o.x + r.x, 0.f);
        o.y = fmaxf(o.y + r.y, 0.f);
        o.z = fmaxf(o.z + r.z, 0.f);
        o.w = fmaxf(o.w + r.w, 0.f);
    }
    *(float4*)(outp + (size_t)n * D + lane * 4) = o;
}

// ---------------- launch ----------------
extern "C" void kernel_launch(void* const* d_in, const int* in_sizes, int n_in,
                              void* d_out, int out_size) {
    const float* x   = (const float*)d_in[0];
    const int*   ei  = (const int*)  d_in[1];
    const float* w0  = (const float*)d_in[2];
    const float* b0  = (const float*)d_in[3];
    const float* w1  = (const float*)d_in[4];
    const float* as1 = (const float*)d_in[5];
    const float* ad1 = (const float*)d_in[6];
    const float* b1  = (const float*)d_in[7];
    const float* w2  = (const float*)d_in[8];
    const float* as2 = (const float*)d_in[9];
    const float* ad2 = (const float*)d_in[10];
    const float* b2  = (const float*)d_in[11];
    const float* w3  = (const float*)d_in[12];
    const float* as3 = (const float*)d_in[13];
    const float* ad3 = (const float*)d_in[14];
    const float* b3  = (const float*)d_in[15];
    float* out = (float*)d_out;

    // CSR by destination (rebuilt every replay; deterministic counts)
    k_init<<<(N_NODES + 255) / 256, 256>>>();
    k_count<<<(N_EDGES + 255) / 256, 256>>>(ei);
    int nb = (N_NODES + 1023) / 1024;
    k_scan1<<<nb, 1024>>>();
    k_scan2<<<1, 64>>>(nb);
    k_scan3<<<(N_NODES + 255) / 256, 256>>>();
    k_scatter<<<(N_NODES + N_EDGES + 255) / 256, 256>>>(ei);

    int ggrid = (N_NODES + 127) / 128;      // 391 blocks
    int wgrid = (N_NODES * 32) / 256;       // 6250 blocks, 1 warp per node

    // h0 = x @ w0 + b0  -> g_h
    k_gemm_tc<<<ggrid, 256>>>(x, 0, w0, b0, 0);

    // layer 1: in g_h -> out g_h2 (relu + residual)
    k_gemm_tc<<<ggrid, 256>>>(nullptr, 0, w1, nullptr, 2);
    k_al<<<wgrid, 256>>>(as1, ad1);
    k_agg<<<wgrid, 256>>>(0, nullptr, 1, b1, 1);

    // layer 2: in g_h2 -> out g_h (relu + residual)
    k_gemm_tc<<<ggrid, 256>>>(nullptr, 1, w2, nullptr, 2);
    k_al<<<wgrid, 256>>>(as2, ad2);
    k_agg<<<wgrid, 256>>>(1, nullptr, 0, b2, 1);

    // layer 3: in g_h -> d_out (plain)
    k_gemm_tc<<<ggrid, 256>>>(nullptr, 0, w3, nullptr, 2);
    k_al<<<wgrid, 256>>>(as3, ad3);
    k_agg<<<wgrid, 256>>>(0, out, 0, b3, 0);
}

// round 3
// speedup vs baseline: 1.6266x; 1.0357x over previous
#include <cuda_runtime.h>
#include <cuda_fp16.h>
#include <cstdint>

#define N_NODES 50000
#define N_EDGES 800000
#define E_TOT   (N_EDGES + N_NODES)
#define D 128
#define H 4

// ---------------- scratch (static device globals; no allocs) ----------------
__device__ __align__(16) float  g_h  [N_NODES * D];
__device__ __align__(16) float  g_h2 [N_NODES * D];
__device__ __align__(16) __half g_xph[N_NODES * D];   // fp16 message mirror
__device__ __align__(16) float  g_als[N_NODES * H];
__device__ __align__(16) float  g_ald[N_NODES * H];
__device__ int g_deg[N_NODES];
__device__ int g_rowptr[N_NODES + 1];
__device__ int g_wp[N_NODES];
__device__ int g_col[E_TOT];
__device__ int g_bsum[64];

// ---------------- CSR build ----------------
__global__ void k_init() {
    int i = blockIdx.x * blockDim.x + threadIdx.x;
    if (i < N_NODES) g_deg[i] = 1;            // self loop pre-counted
}

__global__ void k_count(const int* __restrict__ ei) {
    int i = blockIdx.x * blockDim.x + threadIdx.x;
    if (i < N_EDGES) atomicAdd(&g_deg[ei[N_EDGES + i]], 1);
}

__global__ void k_scan1() {
    __shared__ int sm[1024];
    int i = blockIdx.x * 1024 + threadIdx.x;
    int v = (i < N_NODES) ? g_deg[i] : 0;
    sm[threadIdx.x] = v;
    __syncthreads();
    for (int off = 1; off < 1024; off <<= 1) {
        int t = (threadIdx.x >= off) ? sm[threadIdx.x - off] : 0;
        __syncthreads();
        sm[threadIdx.x] += t;
        __syncthreads();
    }
    if (i < N_NODES) g_rowptr[i] = sm[threadIdx.x] - v;   // exclusive
    if (threadIdx.x == 1023) g_bsum[blockIdx.x] = sm[1023];
}

__global__ void k_scan2(int nb) {          // parallel 64-wide Hillis-Steele
    __shared__ int sm[64];
    int t = threadIdx.x;
    int v = (t < nb) ? g_bsum[t] : 0;
    sm[t] = v;
    __syncthreads();
#pragma unroll
    for (int off = 1; off < 64; off <<= 1) {
        int x = (t >= off) ? sm[t - off] : 0;
        __syncthreads();
        sm[t] += x;
        __syncthreads();
    }
    if (t < nb) g_bsum[t] = sm[t] - v;     // exclusive block offsets
}

__global__ void k_scan3() {
    int i = blockIdx.x * blockDim.x + threadIdx.x;
    if (i < N_NODES) {
        int r = g_rowptr[i] + g_bsum[i >> 10];
        g_rowptr[i] = r;
        g_wp[i] = r;
    }
    if (i == 0) g_rowptr[N_NODES] = E_TOT;
}

__global__ void k_scatter(const int* __restrict__ ei) {
    int i = blockIdx.x * blockDim.x + threadIdx.x;
    if (i < N_NODES) {
        int p = atomicAdd(&g_wp[i], 1);
        g_col[p] = i;                          // self loop
    } else if (i < N_NODES + N_EDGES) {
        int j = i - N_NODES;
        int s = ei[j], d = ei[N_EDGES + j];
        int p = atomicAdd(&g_wp[d], 1);
        g_col[p] = s;
    }
}

// ---------------- tf32 tensor-core GEMM ----------------
// C[N,128] = A[N,128] @ W[128,128], BM=128 BN=128 BK=32, 256 thr.
// 8 warps: warp_m = wid&3 (32 rows), warp_n = wid>>2 (64 cols).
// mma.sync.aligned.m16n8k8 tf32.
//
// Two epilogues:
//   asrc == null : fp32 store (+bias) into g_h / g_h2
//   asrc != null : GAT "xp" mode — fp16 mirror store into g_xph, plus fused
//                  attention logits al_src/al_dst. Each warp's 64 columns
//                  cover exactly 2 heads (C=32), so per-head dots complete
//                  within one warp: quad shuffle-reduce, direct store,
//                  no atomics, no zeroing.

__device__ __forceinline__ uint32_t f2tf32(float f) {
    uint32_t r;
    asm("cvt.rna.tf32.f32 %0, %1;" : "=r"(r) : "f"(f));
    return r;
}

__global__ void __launch_bounds__(256) k_gemm_tc(
        const float* Aext, int asel,
        const float* __restrict__ W,
        const float* __restrict__ bias,
        int csel,
        const float* __restrict__ asrc,
        const float* __restrict__ adst) {
    __shared__ uint32_t As[128 * 36];   // [m][k], stride 36
    __shared__ uint32_t Bs[32 * 136];   // [k][n], stride 136

    const float* A = Aext ? Aext : (asel == 0 ? g_h : g_h2);
    float* Cp = (csel == 0 ? g_h : g_h2);

    const int bm = blockIdx.x * 128;
    const int tid = threadIdx.x;
    const int wid = tid >> 5, lane = tid & 31;
    const int g = lane >> 2, tig = lane & 3;
    const int wm = (wid & 3) * 32;       // warp row base within tile
    const int wn = (wid >> 2) * 64;      // warp col base within tile

    float acc[2][8][4];
#pragma unroll
    for (int mt = 0; mt < 2; mt++)
#pragma unroll
        for (int nt = 0; nt < 8; nt++)
#pragma unroll
            for (int q = 0; q < 4; q++) acc[mt][nt][q] = 0.f;

    for (int k0 = 0; k0 < 128; k0 += 32) {
#pragma unroll
        for (int it = 0; it < 4; it++) {
            int idx = tid + 256 * it;
            int row = idx >> 3, c4 = (idx & 7) << 2;
            float4 v = make_float4(0.f, 0.f, 0.f, 0.f);
            if (bm + row < N_NODES)
                v = *(const float4*)(A + (size_t)(bm + row) * D + k0 + c4);
            uint32_t* p = &As[row * 36 + c4];
            p[0] = f2tf32(v.x); p[1] = f2tf32(v.y);
            p[2] = f2tf32(v.z); p[3] = f2tf32(v.w);
        }
#pragma unroll
        for (int it = 0; it < 4; it++) {
            int idx = tid + 256 * it;
            int row = idx >> 5, c4 = (idx & 31) << 2;
            float4 v = *(const float4*)(W + (size_t)(k0 + row) * D + c4);
            uint32_t* p = &Bs[row * 136 + c4];
            p[0] = f2tf32(v.x); p[1] = f2tf32(v.y);
            p[2] = f2tf32(v.z); p[3] = f2tf32(v.w);
        }
        __syncthreads();

#pragma unroll
        for (int kk = 0; kk < 32; kk += 8) {
            uint32_t a[2][4], b[8][2];
#pragma unroll
            for (int mt = 0; mt < 2; mt++) {
                int r0 = wm + mt * 16 + g;
                a[mt][0] = As[r0 * 36 + kk + tig];
                a[mt][1] = As[(r0 + 8) * 36 + kk + tig];
                a[mt][2] = As[r0 * 36 + kk + tig + 4];
                a[mt][3] = As[(r0 + 8) * 36 + kk + tig + 4];
            }
#pragma unroll
            for (int nt = 0; nt < 8; nt++) {
                int c0 = wn + nt * 8 + g;
                b[nt][0] = Bs[(kk + tig) * 136 + c0];
                b[nt][1] = Bs[(kk + tig + 4) * 136 + c0];
            }
#pragma unroll
            for (int mt = 0; mt < 2; mt++)
#pragma unroll
                for (int nt = 0; nt < 8; nt++) {
                    asm volatile(
                        "mma.sync.aligned.m16n8k8.row.col.f32.tf32.tf32.f32 "
                        "{%0,%1,%2,%3}, {%4,%5,%6,%7}, {%8,%9}, {%0,%1,%2,%3};"
                        : "+f"(acc[mt][nt][0]), "+f"(acc[mt][nt][1]),
                          "+f"(acc[mt][nt][2]), "+f"(acc[mt][nt][3])
                        : "r"(a[mt][0]), "r"(a[mt][1]),
                          "r"(a[mt][2]), "r"(a[mt][3]),
                          "r"(b[nt][0]), "r"(b[nt][1]));
                }
        }
        __syncthreads();
    }

    if (asrc == nullptr) {
        // plain fp32 epilogue (+ optional bias)
#pragma unroll
        for (int mt = 0; mt < 2; mt++) {
            int row = bm + wm + mt * 16 + g;
#pragma unroll
            for (int nt = 0; nt < 8; nt++) {
                int col = wn + nt * 8 + 2 * tig;
                float bx = bias ? bias[col] : 0.f;
                float by = bias ? bias[col + 1] : 0.f;
                if (row < N_NODES)
                    *(float2*)(Cp + (size_t)row * D + col) =
                        make_float2(acc[mt][nt][0] + bx, acc[mt][nt][1] + by);
                if (row + 8 < N_NODES)
                    *(float2*)(Cp + (size_t)(row + 8) * D + col) =
                        make_float2(acc[mt][nt][2] + bx, acc[mt][nt][3] + by);
            }
        }
    } else {
        // xp epilogue: fp16 mirror + fused attention logits.
        const int head_base = (wn == 0) ? 0 : 2;
#pragma unroll
        for (int mt = 0; mt < 2; mt++) {
#pragma unroll
            for (int rh = 0; rh < 2; rh++) {          // row / row+8 halves
                int row = bm + wm + mt * 16 + rh * 8 + g;
                float ps0 = 0.f, ps1 = 0.f, pd0 = 0.f, pd1 = 0.f;
#pragma unroll
                for (int nt = 0; nt < 8; nt++) {
                    int col = wn + nt * 8 + 2 * tig;
                    int c = (nt & 3) * 8 + 2 * tig;   // channel within head
                    int hl = nt >> 2;                 // head-local (0/1)
                    float v0 = acc[mt][nt][rh * 2 + 0];
                    float v1 = acc[mt][nt][rh * 2 + 1];
                    float s0 = __ldg(asrc + (head_base + hl) * 32 + c);
                    float s1 = __ldg(asrc + (head_base + hl) * 32 + c + 1);
                    float d0 = __ldg(adst + (head_base + hl) * 32 + c);
                    float d1 = __ldg(adst + (head_base + hl) * 32 + c + 1);
                    if (hl == 0) { ps0 += v0 * s0 + v1 * s1; pd0 += v0 * d0 + v1 * d1; }
                    else         { ps1 += v0 * s0 + v1 * s1; pd1 += v0 * d0 + v1 * d1; }
                    if (row < N_NODES)
                        *(__half2*)(g_xph + (size_t)row * D + col) =
                            __floats2half2_rn(v0, v1);
                }
                // quad reduce (lanes g*4 + tig, offsets 1,2 stay in quad)
#pragma unroll
                for (int off = 1; off < 4; off <<= 1) {
                    ps0 += __shfl_xor_sync(0xffffffffu, ps0, off);
                    ps1 += __shfl_xor_sync(0xffffffffu, ps1, off);
                    pd0 += __shfl_xor_sync(0xffffffffu, pd0, off);
                    pd1 += __shfl_xor_sync(0xffffffffu, pd1, off);
                }
                if (tig == 0 && row < N_NODES) {
                    g_als[row * 4 + head_base]     = ps0;
                    g_als[row * 4 + head_base + 1] = ps1;
                    g_ald[row * 4 + head_base]     = pd0;
                    g_ald[row * 4 + head_base + 1] = pd1;
                }
            }
        }
    }
}

// ---------------- softmax-aggregate: one warp per destination node ----------------
// Single pass, no max subtraction (logits bounded, exp cannot overflow).
// Messages gathered in fp16 (256 B/edge): downstream tf32 GEMM truncates to
// 10 mantissa bits anyway, so no additional end-to-end precision class lost.
__global__ void k_agg(int in_sel, float* out_ext, int out_sel,
                      const float* __restrict__ bias, int relu_res) {
    int n = (blockIdx.x * blockDim.x + threadIdx.x) >> 5;
    if (n >= N_NODES) return;
    int lane = threadIdx.x & 31;
    const float* xin = (in_sel == 0) ? g_h : g_h2;
    float* outp = out_ext ? out_ext : (out_sel == 0 ? g_h : g_h2);
    int beg = g_rowptr[n], end = g_rowptr[n + 1];
    int hh = lane >> 3;
    float ad = g_ald[n * 4 + hh];

    float4 acc = make_float4(0.f, 0.f, 0.f, 0.f);
    float ssum = 0.f;
    int s_next = (beg < end) ? g_col[beg] : 0;
    for (int j = beg; j < end; j++) {
        int s = s_next;
        if (j + 1 < end) s_next = g_col[j + 1];       // prefetch next index
        float e = g_als[(size_t)s * 4 + hh] + ad;
        e = e > 0.f ? e : 0.2f * e;
        float p = __expf(e);
        ssum += p;
        uint2 u = *(const uint2*)(g_xph + (size_t)s * D + lane * 4);
        float2 f0 = __half22float2(*(__half2*)&u.x);
        float2 f1 = __half22float2(*(__half2*)&u.y);
        acc.x += p * f0.x; acc.y += p * f0.y;
        acc.z += p * f1.x; acc.w += p * f1.y;
    }
    float inv = 1.f / ssum;
    float4 bv = *(const float4*)(bias + lane * 4);
    float4 o;
    o.x = acc.x * inv + bv.x;
    o.y = acc.y * inv + bv.y;
    o.z = acc.z * inv + bv.z;
    o.w = acc.w * inv + bv.w;
    if (relu_res) {
        float4 r = *(const float4*)(xin + (size_t)n * D + lane * 4);
        o.x = fmaxf(o.x + r.x, 0.f);
        o.y = fmaxf(o.y + r.y, 0.f);
        o.z = fmaxf(o.z + r.z, 0.f);
        o.w = fmaxf(o.w + r.w, 0.f);
    }
    *(float4*)(outp + (size_t)n * D + lane * 4) = o;
}

// ---------------- launch ----------------
extern "C" void kernel_launch(void* const* d_in, const int* in_sizes, int n_in,
                              void* d_out, int out_size) {
    const float* x   = (const float*)d_in[0];
    const int*   ei  = (const int*)  d_in[1];
    const float* w0  = (const float*)d_in[2];
    const float* b0  = (const float*)d_in[3];
    const float* w1  = (const float*)d_in[4];
    const float* as1 = (const float*)d_in[5];
    const float* ad1 = (const float*)d_in[6];
    const float* b1  = (const float*)d_in[7];
    const float* w2  = (const float*)d_in[8];
    const float* as2 = (const float*)d_in[9];
    const float* ad2 = (const float*)d_in[10];
    const float* b2  = (const float*)d_in[11];
    const float* w3  = (const float*)d_in[12];
    const float* as3 = (const float*)d_in[13];
    const float* ad3 = (const float*)d_in[14];
    const float* b3  = (const float*)d_in[15];
    float* out = (float*)d_out;

    // CSR by destination (rebuilt every replay; deterministic counts)
    k_init<<<(N_NODES + 255) / 256, 256>>>();
    k_count<<<(N_EDGES + 255) / 256, 256>>>(ei);
    int nb = (N_NODES + 1023) / 1024;
    k_scan1<<<nb, 1024>>>();
    k_scan2<<<1, 64>>>(nb);
    k_scan3<<<(N_NODES + 255) / 256, 256>>>();
    k_scatter<<<(N_NODES + N_EDGES + 255) / 256, 256>>>(ei);

    int ggrid = (N_NODES + 127) / 128;      // 391 blocks
    int wgrid = (N_NODES * 32) / 256;       // 6250 blocks, 1 warp per node

    // h0 = x @ w0 + b0  -> g_h
    k_gemm_tc<<<ggrid, 256>>>(x, 0, w0, b0, 0, nullptr, nullptr);

    // layer 1: in g_h -> out g_h2 (relu + residual)
    k_gemm_tc<<<ggrid, 256>>>(nullptr, 0, w1, nullptr, 2, as1, ad1);
    k_agg<<<wgrid, 256>>>(0, nullptr, 1, b1, 1);

    // layer 2: in g_h2 -> out g_h (relu + residual)
    k_gemm_tc<<<ggrid, 256>>>(nullptr, 1, w2, nullptr, 2, as2, ad2);
    k_agg<<<wgrid, 256>>>(1, nullptr, 0, b2, 1);

    // layer 3: in g_h -> d_out (plain)
    k_gemm_tc<<<ggrid, 256>>>(nullptr, 0, w3, nullptr, 2, as3, ad3);
    k_agg<<<wgrid, 256>>>(0, out, 0, b3, 0);
}